// round 2
// baseline (speedup 1.0000x reference)
#include <cuda_runtime.h>
#include <math.h>

#define N_BATCH 4
#define SEQ     4096
#define HID     1024
#define NHEADS  16
#define HDIM    64
#define MROWS   (N_BATCH * SEQ)   // 16384

// ---------------- scratch (device globals: no allocation allowed) ----------
__device__ float g_Q[N_BATCH * SEQ * HID];
__device__ float g_K[N_BATCH * SEQ * HID];
__device__ float g_V[N_BATCH * SEQ * HID];
__device__ float g_Y[N_BATCH * SEQ * HID];
__device__ float g_E[N_BATCH * NHEADS * NHEADS];
__device__ float g_A[N_BATCH * NHEADS * NHEADS];

// ---------------- SGEMM: C[M,N] = A[M,K] @ B[K,N] (+ bias[N]) --------------
// 128x128 block tile, BK=8, 256 threads, 8x8 register tile per thread.
#define BM 128
#define BN 128
#define BK 8
#define TM 8
#define TN 8

__global__ __launch_bounds__(256, 2)
void sgemm_bias(const float* __restrict__ A, const float* __restrict__ B,
                const float* __restrict__ bias, float* __restrict__ C,
                int M, int N, int K)
{
    __shared__ float As[BK][BM];
    __shared__ float Bs[BK][BN];

    const int tid  = threadIdx.x;
    const int tRow = tid / (BN / TN);   // 0..15
    const int tCol = tid % (BN / TN);   // 0..15

    A += (size_t)blockIdx.y * BM * K;
    B += (size_t)blockIdx.x * BN;
    C += (size_t)blockIdx.y * BM * N + (size_t)blockIdx.x * BN;

    // load-index mapping
    const int aRow = tid >> 1;          // 0..127
    const int aCol = (tid & 1) * 4;     // 0 or 4
    const int bRow = tid >> 5;          // 0..7
    const int bCol = (tid & 31) * 4;    // 0..124

    float acc[TM][TN];
#pragma unroll
    for (int i = 0; i < TM; i++)
#pragma unroll
        for (int j = 0; j < TN; j++) acc[i][j] = 0.0f;

    for (int k0 = 0; k0 < K; k0 += BK) {
        float4 av = *reinterpret_cast<const float4*>(A + (size_t)aRow * K + k0 + aCol);
        As[aCol + 0][aRow] = av.x;
        As[aCol + 1][aRow] = av.y;
        As[aCol + 2][aRow] = av.z;
        As[aCol + 3][aRow] = av.w;
        float4 bv = *reinterpret_cast<const float4*>(B + (size_t)(k0 + bRow) * N + bCol);
        *reinterpret_cast<float4*>(&Bs[bRow][bCol]) = bv;
        __syncthreads();

#pragma unroll
        for (int k = 0; k < BK; k++) {
            float4 a0 = *reinterpret_cast<const float4*>(&As[k][tRow * TM]);
            float4 a1 = *reinterpret_cast<const float4*>(&As[k][tRow * TM + 4]);
            float4 b0 = *reinterpret_cast<const float4*>(&Bs[k][tCol * TN]);
            float4 b1 = *reinterpret_cast<const float4*>(&Bs[k][tCol * TN + 4]);
            float rm[TM] = {a0.x, a0.y, a0.z, a0.w, a1.x, a1.y, a1.z, a1.w};
            float rn[TN] = {b0.x, b0.y, b0.z, b0.w, b1.x, b1.y, b1.z, b1.w};
#pragma unroll
            for (int i = 0; i < TM; i++)
#pragma unroll
                for (int j = 0; j < TN; j++)
                    acc[i][j] = fmaf(rm[i], rn[j], acc[i][j]);
        }
        __syncthreads();
    }

    float bb[TN];
#pragma unroll
    for (int j = 0; j < TN; j++)
        bb[j] = bias ? bias[(size_t)blockIdx.x * BN + tCol * TN + j] : 0.0f;

#pragma unroll
    for (int i = 0; i < TM; i++) {
        int row = tRow * TM + i;
#pragma unroll
        for (int j = 0; j < TN; j += 4) {
            int col = tCol * TN + j;
            float4 o;
            o.x = acc[i][j + 0] + bb[j + 0];
            o.y = acc[i][j + 1] + bb[j + 1];
            o.z = acc[i][j + 2] + bb[j + 2];
            o.w = acc[i][j + 3] + bb[j + 3];
            *reinterpret_cast<float4*>(C + (size_t)row * N + col) = o;
        }
    }
}

// ---------------- energy[n,a,b] = sum_{s,d} Q[n,s,a*64+d]*K[n,s,b*64+d] ----
// grid (N_BATCH, SEQ/ECHUNK), 256 threads; thread owns pair (a,b), a=tid&15.
#define ECHUNK 16

__global__ __launch_bounds__(256)
void energy_kernel()
{
    const int n  = blockIdx.x;
    const int s0 = blockIdx.y * ECHUNK;
    const int tid = threadIdx.x;
    const int a = tid & 15;
    const int b = tid >> 4;

    // transposed + padded smem: qs[d*17 + head]  -> conflict-free reads
    __shared__ float qs[64 * 17];
    __shared__ float ks[64 * 17];

    const float* Qb = g_Q + (size_t)n * SEQ * HID;
    const float* Kb = g_K + (size_t)n * SEQ * HID;

    float acc = 0.0f;
    for (int s = s0; s < s0 + ECHUNK; s++) {
#pragma unroll
        for (int i = 0; i < 4; i++) {
            int c = tid + i * 256;                     // 0..1023
            int d = c & 63, h = c >> 6;                // channel = h*64+d
            qs[d * 17 + h] = Qb[(size_t)s * HID + c];
            ks[d * 17 + h] = Kb[(size_t)s * HID + c];
        }
        __syncthreads();
#pragma unroll
        for (int d = 0; d < 64; d++)
            acc = fmaf(qs[d * 17 + a], ks[d * 17 + b], acc);
        __syncthreads();
    }
    atomicAdd(&g_E[n * 256 + a * 16 + b], acc);
}

// ---------------- softmax over b: attn = softmax(E / sqrt(64)) -------------
__global__ void softmax_kernel()
{
    int t = threadIdx.x;                  // 64 threads: (n, a)
    if (t >= N_BATCH * NHEADS) return;
    int n = t >> 4, a = t & 15;
    const float* e = g_E + n * 256 + a * 16;
    float v[16], m = -1e30f;
#pragma unroll
    for (int b = 0; b < 16; b++) { v[b] = e[b] * 0.125f; m = fmaxf(m, v[b]); }
    float s = 0.0f;
#pragma unroll
    for (int b = 0; b < 16; b++) { v[b] = expf(v[b] - m); s += v[b]; }
    float inv = 1.0f / s;
    float* o = g_A + n * 256 + a * 16;
#pragma unroll
    for (int b = 0; b < 16; b++) o[b] = v[b] * inv;
}

// ---------------- Y[n, a*256+u, r*64+d] = sum_b attn[n,a,b] V[n,16u+r,b*64+d]
// (faithful torch .reshape of [N,H,S,D] -> [N,S,HID]); grid (N_BATCH, 256)=(n,u)
__global__ __launch_bounds__(256)
void y_kernel()
{
    const int n = blockIdx.x, u = blockIdx.y;
    __shared__ float at[256];
    at[threadIdx.x] = g_A[n * 256 + threadIdx.x];
    __syncthreads();

    const float* Vb = g_V + ((size_t)n * SEQ + (size_t)u * 16) * HID;
    float*       Yb = g_Y + (size_t)n * SEQ * HID + (size_t)u * HID;

    for (int j = threadIdx.x; j < HID; j += 256) {
        int r = j >> 6, d = j & 63;
        float v[16];
#pragma unroll
        for (int b = 0; b < 16; b++)
            v[b] = Vb[(size_t)r * HID + b * 64 + d];
#pragma unroll
        for (int a = 0; a < 16; a++) {
            float acc = 0.0f;
#pragma unroll
            for (int b = 0; b < 16; b++)
                acc = fmaf(at[a * 16 + b], v[b], acc);
            Yb[(size_t)a * 256 * HID + j] = acc;
        }
    }
}

// ---------------- launch ----------------------------------------------------
extern "C" void kernel_launch(void* const* d_in, const int* in_sizes, int n_in,
                              void* d_out, int out_size)
{
    const float* x  = (const float*)d_in[0];
    const float* Wq = (const float*)d_in[1];
    const float* Wk = (const float*)d_in[2];
    const float* Wv = (const float*)d_in[3];
    const float* Wo = (const float*)d_in[4];
    const float* bo = (const float*)d_in[5];
    float* out = (float*)d_out;

    float *pQ, *pK, *pV, *pY, *pE;
    cudaGetSymbolAddress((void**)&pQ, g_Q);
    cudaGetSymbolAddress((void**)&pK, g_K);
    cudaGetSymbolAddress((void**)&pV, g_V);
    cudaGetSymbolAddress((void**)&pY, g_Y);
    cudaGetSymbolAddress((void**)&pE, g_E);

    dim3 gGemm(HID / BN, MROWS / BM);   // (8, 128)
    sgemm_bias<<<gGemm, 256>>>(x, Wq, nullptr, pQ, MROWS, HID, HID);
    sgemm_bias<<<gGemm, 256>>>(x, Wk, nullptr, pK, MROWS, HID, HID);
    sgemm_bias<<<gGemm, 256>>>(x, Wv, nullptr, pV, MROWS, HID, HID);

    cudaMemsetAsync(pE, 0, N_BATCH * NHEADS * NHEADS * sizeof(float), 0);
    energy_kernel<<<dim3(N_BATCH, SEQ / ECHUNK), 256>>>();
    softmax_kernel<<<1, 64>>>();
    y_kernel<<<dim3(N_BATCH, SEQ / 16), 256>>>();

    sgemm_bias<<<gGemm, 256>>>(pY, Wo, bo, out, MROWS, HID, HID);
}

// round 4
// speedup vs baseline: 2.9335x; 2.9335x over previous
#include <cuda_runtime.h>
#include <cuda_bf16.h>
#include <math.h>
#include <stdint.h>

#define N_BATCH 4
#define SEQ     4096
#define HID     1024
#define NHEADS  16
#define MROWS   (N_BATCH * SEQ)   // 16384

// ---------------- scratch (device globals: no allocation allowed) ----------
__device__ float          g_Q [MROWS * HID];
__device__ float          g_K [MROWS * HID];
__device__ float          g_V [MROWS * HID];
__device__ __nv_bfloat16  g_xh[MROWS * HID];
__device__ __nv_bfloat16  g_xl[MROWS * HID];
__device__ __nv_bfloat16  g_Yh[MROWS * HID];
__device__ __nv_bfloat16  g_Yl[MROWS * HID];
__device__ __nv_bfloat16  g_Wth[4 * HID * HID];   // transposed [N,K] hi
__device__ __nv_bfloat16  g_Wtl[4 * HID * HID];   // transposed [N,K] lo
__device__ float          g_E [N_BATCH * NHEADS * NHEADS];
__device__ float          g_A [N_BATCH * NHEADS * NHEADS];

// ======================= PTX helpers (baseline ISA, no 'a' features) =======
__device__ __forceinline__ uint32_t smem_u32(const void* p) {
    uint32_t a;
    asm("{ .reg .u64 t; cvta.to.shared.u64 t, %1; cvt.u32.u64 %0, t; }" : "=r"(a) : "l"(p));
    return a;
}
#define SWZ128(o) ((o) ^ (((o) >> 3) & 0x70))

__device__ __forceinline__ void cp_async16(uint32_t dst, const void* src) {
    asm volatile("cp.async.cg.shared.global [%0], [%1], 16;" :: "r"(dst), "l"(src));
}
#define CP_COMMIT() asm volatile("cp.async.commit_group;" ::: "memory")
#define CP_WAIT(n)  asm volatile("cp.async.wait_group %0;" :: "n"(n) : "memory")

__device__ __forceinline__ void ldsm_x4(uint32_t* r, uint32_t addr) {
    asm volatile("ldmatrix.sync.aligned.m8n8.x4.shared.b16 {%0,%1,%2,%3}, [%4];"
        : "=r"(r[0]), "=r"(r[1]), "=r"(r[2]), "=r"(r[3]) : "r"(addr));
}
__device__ __forceinline__ void mma_bf16(float* d, const uint32_t* a, const uint32_t* b) {
    asm volatile(
        "mma.sync.aligned.m16n8k16.row.col.f32.bf16.bf16.f32 "
        "{%0,%1,%2,%3}, {%4,%5,%6,%7}, {%8,%9}, {%0,%1,%2,%3};"
        : "+f"(d[0]), "+f"(d[1]), "+f"(d[2]), "+f"(d[3])
        : "r"(a[0]), "r"(a[1]), "r"(a[2]), "r"(a[3]), "r"(b[0]), "r"(b[1]));
}

// ======================= bf16x3 GEMM (HMMA) ================================
// C[M,1024](fp32) = (Ah+Al)[M,1024] @ (Bth+Btl)[1024,1024]^T  (+ bias)
// CTA 128x128, BK=64 bf16 (128B SW128 rows), double-buffered cp.async,
// 8 warps (2 M x 4 N), warp tile 64x32, mma.sync m16n8k16 bf16.
#define STAGE_BYTES 65536          // Ah,Al,Bh,Bl x 16KB
#define GEMM_SMEM   (2 * STAGE_BYTES)   // 131072

__global__ __launch_bounds__(256, 1)
void gemm_bf16x3(const __nv_bfloat16* __restrict__ Agh,
                 const __nv_bfloat16* __restrict__ Agl,
                 const __nv_bfloat16* __restrict__ Bgh,
                 const __nv_bfloat16* __restrict__ Bgl,
                 const float* __restrict__ bias,
                 float* __restrict__ C)
{
    extern __shared__ char smem[];
    const uint32_t sb = smem_u32(smem);
    const int tid  = threadIdx.x;
    const int wid  = tid >> 5, lane = tid & 31;
    const int wr   = wid >> 2;          // 0..1  (M)
    const int wc   = wid & 3;           // 0..3  (N)
    const int rowA0 = blockIdx.y * 128;
    const int rowB0 = blockIdx.x * 128;

    const __nv_bfloat16* gsrc[4] = { Agh + (size_t)rowA0 * HID,
                                     Agl + (size_t)rowA0 * HID,
                                     Bgh + (size_t)rowB0 * HID,
                                     Bgl + (size_t)rowB0 * HID };

    float acc[4][4][4];
#pragma unroll
    for (int mt = 0; mt < 4; mt++)
#pragma unroll
        for (int nt = 0; nt < 4; nt++)
#pragma unroll
            for (int e = 0; e < 4; e++) acc[mt][nt][e] = 0.0f;

    // precomputed per-thread load mapping (16 x 16B chunks per stage)
    // c = tid + i*256; mat = c>>10; j = c&1023; row = j>>3; q = j&7
    // prologue: issue stage 0
    {
        const int k0 = 0;
#pragma unroll
        for (int i = 0; i < 16; i++) {
            int c = tid + i * 256;
            int mat = c >> 10, j = c & 1023, row = j >> 3, q = j & 7;
            uint32_t dst = sb + mat * 16384 + SWZ128((uint32_t)(row * 128 + q * 16));
            cp_async16(dst, gsrc[mat] + (size_t)row * HID + k0 + q * 8);
        }
        CP_COMMIT();
    }

    for (int s = 0; s < 16; s++) {
        if (s < 15) {
            const int k0 = (s + 1) * 64;
            const uint32_t bufb = sb + ((s + 1) & 1) * STAGE_BYTES;
#pragma unroll
            for (int i = 0; i < 16; i++) {
                int c = tid + i * 256;
                int mat = c >> 10, j = c & 1023, row = j >> 3, q = j & 7;
                uint32_t dst = bufb + mat * 16384 + SWZ128((uint32_t)(row * 128 + q * 16));
                cp_async16(dst, gsrc[mat] + (size_t)row * HID + k0 + q * 8);
            }
            CP_COMMIT();
            CP_WAIT(1);
        } else {
            CP_WAIT(0);
        }
        __syncthreads();

        const uint32_t stg = sb + (s & 1) * STAGE_BYTES;
        const int arow = wr * 64 + (lane & 15);
        const int brow = wc * 32 + (lane & 7) + ((lane >> 4) << 3);

#pragma unroll
        for (int ks = 0; ks < 4; ks++) {
            uint32_t ah[4][4], al[4][4], bh[2][4], bl[2][4];
            const int abo = ks * 32 + (lane >> 4) * 16;
            const int bbo = ks * 32 + ((lane >> 3) & 1) * 16;
#pragma unroll
            for (int mt = 0; mt < 4; mt++) {
                uint32_t off = SWZ128((uint32_t)((arow + mt * 16) * 128 + abo));
                ldsm_x4(ah[mt], stg + off);
                ldsm_x4(al[mt], stg + 16384 + off);
            }
#pragma unroll
            for (int bt = 0; bt < 2; bt++) {
                uint32_t off = SWZ128((uint32_t)((brow + bt * 16) * 128 + bbo));
                ldsm_x4(bh[bt], stg + 32768 + off);
                ldsm_x4(bl[bt], stg + 49152 + off);
            }
#pragma unroll
            for (int mt = 0; mt < 4; mt++)
#pragma unroll
                for (int nt = 0; nt < 4; nt++) {
                    const uint32_t* bhp = &bh[nt >> 1][(nt & 1) * 2];
                    const uint32_t* blp = &bl[nt >> 1][(nt & 1) * 2];
                    mma_bf16(acc[mt][nt], ah[mt], bhp);
                    mma_bf16(acc[mt][nt], ah[mt], blp);
                    mma_bf16(acc[mt][nt], al[mt], bhp);
                }
        }
        __syncthreads();
    }

    // -------- epilogue: regs -> SMEM (padded) -> coalesced STG -------------
    float* Cs = reinterpret_cast<float*>(smem);   // [128][132]
    {
        const int r0 = wr * 64 + (lane >> 2);
        const int c0 = wc * 32 + (lane & 3) * 2;
#pragma unroll
        for (int mt = 0; mt < 4; mt++)
#pragma unroll
            for (int nt = 0; nt < 4; nt++) {
                int r = r0 + mt * 16;
                int c = c0 + nt * 8;
                *reinterpret_cast<float2*>(&Cs[r * 132 + c]) =
                    make_float2(acc[mt][nt][0], acc[mt][nt][1]);
                *reinterpret_cast<float2*>(&Cs[(r + 8) * 132 + c]) =
                    make_float2(acc[mt][nt][2], acc[mt][nt][3]);
            }
    }
    __syncthreads();

#pragma unroll
    for (int i = 0; i < 16; i++) {
        int idx = i * 256 + tid;             // 0..4095
        int row = idx >> 5, q = idx & 31;
        float4 v = *reinterpret_cast<const float4*>(&Cs[row * 132 + q * 4]);
        int colg = rowB0 + q * 4;
        if (bias) {
            float4 b = *reinterpret_cast<const float4*>(bias + colg);
            v.x += b.x; v.y += b.y; v.z += b.z; v.w += b.w;
        }
        *reinterpret_cast<float4*>(C + (size_t)(rowA0 + row) * HID + colg) = v;
    }
}

// ================= fp32 -> (hi, lo) bf16 split ==============================
__global__ __launch_bounds__(256)
void convert_split(const float* __restrict__ in,
                   __nv_bfloat16* __restrict__ oh,
                   __nv_bfloat16* __restrict__ ol, int n8)
{
    int i = blockIdx.x * 256 + threadIdx.x;
    if (i >= n8) return;
    const float4 a = reinterpret_cast<const float4*>(in)[i * 2];
    const float4 b = reinterpret_cast<const float4*>(in)[i * 2 + 1];
    float v[8] = {a.x, a.y, a.z, a.w, b.x, b.y, b.z, b.w};
    __nv_bfloat16 h[8], l[8];
#pragma unroll
    for (int k = 0; k < 8; k++) {
        h[k] = __float2bfloat16_rn(v[k]);
        l[k] = __float2bfloat16_rn(v[k] - __bfloat162float(h[k]));
    }
    reinterpret_cast<uint4*>(oh)[i] = *reinterpret_cast<uint4*>(h);
    reinterpret_cast<uint4*>(ol)[i] = *reinterpret_cast<uint4*>(l);
}

// =========== W[K,N] fp32 -> Wt[N,K] bf16 hi/lo (transpose + split) ==========
__global__ __launch_bounds__(256)
void convert_w_t(const float* __restrict__ W,
                 __nv_bfloat16* __restrict__ th,
                 __nv_bfloat16* __restrict__ tl)
{
    __shared__ float tile[32][33];
    int tx = threadIdx.x & 31, ty = threadIdx.x >> 5;   // ty 0..7
    int bx = blockIdx.x, by = blockIdx.y;
#pragma unroll
    for (int i = 0; i < 4; i++) {
        int kl = ty * 4 + i;
        tile[kl][tx] = W[(size_t)(by * 32 + kl) * HID + bx * 32 + tx];
    }
    __syncthreads();
#pragma unroll
    for (int i = 0; i < 4; i++) {
        int nl = ty * 4 + i;
        float v = tile[tx][nl];
        __nv_bfloat16 h = __float2bfloat16_rn(v);
        size_t o = (size_t)(bx * 32 + nl) * HID + by * 32 + tx;
        th[o] = h;
        tl[o] = __float2bfloat16_rn(v - __bfloat162float(h));
    }
}

// ---------------- energy[n,a,b] = sum_{s,d} Q[n,s,a*64+d]*K[n,s,b*64+d] ----
#define ECHUNK 16
__global__ __launch_bounds__(256)
void energy_kernel()
{
    const int n  = blockIdx.x;
    const int s0 = blockIdx.y * ECHUNK;
    const int tid = threadIdx.x;
    const int a = tid & 15, b = tid >> 4;

    __shared__ float qs[64 * 17];
    __shared__ float ks[64 * 17];

    const float* Qb = g_Q + (size_t)n * SEQ * HID;
    const float* Kb = g_K + (size_t)n * SEQ * HID;

    float acc = 0.0f;
    for (int s = s0; s < s0 + ECHUNK; s++) {
#pragma unroll
        for (int i = 0; i < 4; i++) {
            int c = tid + i * 256;
            int d = c & 63, h = c >> 6;
            qs[d * 17 + h] = Qb[(size_t)s * HID + c];
            ks[d * 17 + h] = Kb[(size_t)s * HID + c];
        }
        __syncthreads();
#pragma unroll
        for (int d = 0; d < 64; d++)
            acc = fmaf(qs[d * 17 + a], ks[d * 17 + b], acc);
        __syncthreads();
    }
    atomicAdd(&g_E[n * 256 + a * 16 + b], acc);
}

// ---------------- softmax over b ------------------------------------------
__global__ void softmax_kernel()
{
    int t = threadIdx.x;
    if (t >= N_BATCH * NHEADS) return;
    int n = t >> 4, a = t & 15;
    const float* e = g_E + n * 256 + a * 16;
    float v[16], m = -1e30f;
#pragma unroll
    for (int b = 0; b < 16; b++) { v[b] = e[b] * 0.125f; m = fmaxf(m, v[b]); }
    float s = 0.0f;
#pragma unroll
    for (int b = 0; b < 16; b++) { v[b] = expf(v[b] - m); s += v[b]; }
    float inv = 1.0f / s;
    float* o = g_A + n * 256 + a * 16;
#pragma unroll
    for (int b = 0; b < 16; b++) o[b] = v[b] * inv;
}

// ------ Y[n, a*256+u, r*64+d] = sum_b attn[n,a,b] V[n,16u+r,b*64+d] --------
// writes split bf16 hi/lo directly (feeds final GEMM)
__global__ __launch_bounds__(256)
void y_kernel()
{
    const int n = blockIdx.x, u = blockIdx.y;
    __shared__ float at[256];
    at[threadIdx.x] = g_A[n * 256 + threadIdx.x];
    __syncthreads();

    const float* Vb = g_V + ((size_t)n * SEQ + (size_t)u * 16) * HID;
    size_t ybase = (size_t)n * SEQ * HID + (size_t)u * HID;

    for (int j = threadIdx.x; j < HID; j += 256) {
        int r = j >> 6, d = j & 63;
        float v[16];
#pragma unroll
        for (int b = 0; b < 16; b++)
            v[b] = Vb[(size_t)r * HID + b * 64 + d];
#pragma unroll
        for (int a = 0; a < 16; a++) {
            float acc = 0.0f;
#pragma unroll
            for (int b = 0; b < 16; b++)
                acc = fmaf(at[a * 16 + b], v[b], acc);
            size_t o = ybase + (size_t)a * 256 * HID + j;
            __nv_bfloat16 h = __float2bfloat16_rn(acc);
            g_Yh[o] = h;
            g_Yl[o] = __float2bfloat16_rn(acc - __bfloat162float(h));
        }
    }
}

// ---------------- launch ----------------------------------------------------
extern "C" void kernel_launch(void* const* d_in, const int* in_sizes, int n_in,
                              void* d_out, int out_size)
{
    const float* x  = (const float*)d_in[0];
    const float* Wq = (const float*)d_in[1];
    const float* Wk = (const float*)d_in[2];
    const float* Wv = (const float*)d_in[3];
    const float* Wo = (const float*)d_in[4];
    const float* bo = (const float*)d_in[5];
    float* out = (float*)d_out;

    float *pQ, *pK, *pV, *pE;
    __nv_bfloat16 *pxh, *pxl, *pYh, *pYl, *pWth, *pWtl;
    cudaGetSymbolAddress((void**)&pQ, g_Q);
    cudaGetSymbolAddress((void**)&pK, g_K);
    cudaGetSymbolAddress((void**)&pV, g_V);
    cudaGetSymbolAddress((void**)&pE, g_E);
    cudaGetSymbolAddress((void**)&pxh, g_xh);
    cudaGetSymbolAddress((void**)&pxl, g_xl);
    cudaGetSymbolAddress((void**)&pYh, g_Yh);
    cudaGetSymbolAddress((void**)&pYl, g_Yl);
    cudaGetSymbolAddress((void**)&pWth, g_Wth);
    cudaGetSymbolAddress((void**)&pWtl, g_Wtl);

    static int smem_set = 0;
    if (!smem_set) {
        cudaFuncSetAttribute(gemm_bf16x3,
                             cudaFuncAttributeMaxDynamicSharedMemorySize, GEMM_SMEM);
        smem_set = 1;
    }

    const int WSTEP = HID * HID;   // 1M elems per weight

    convert_split<<<(MROWS * HID / 8 + 255) / 256, 256>>>(x, pxh, pxl, MROWS * HID / 8);
    dim3 wgrid(HID / 32, HID / 32);
    convert_w_t<<<wgrid, 256>>>(Wq, pWth + 0 * WSTEP, pWtl + 0 * WSTEP);
    convert_w_t<<<wgrid, 256>>>(Wk, pWth + 1 * WSTEP, pWtl + 1 * WSTEP);
    convert_w_t<<<wgrid, 256>>>(Wv, pWth + 2 * WSTEP, pWtl + 2 * WSTEP);
    convert_w_t<<<wgrid, 256>>>(Wo, pWth + 3 * WSTEP, pWtl + 3 * WSTEP);

    dim3 gg(HID / 128, MROWS / 128);   // (8, 128)
    gemm_bf16x3<<<gg, 256, GEMM_SMEM>>>(pxh, pxl, pWth + 0 * WSTEP, pWtl + 0 * WSTEP, nullptr, pQ);
    gemm_bf16x3<<<gg, 256, GEMM_SMEM>>>(pxh, pxl, pWth + 1 * WSTEP, pWtl + 1 * WSTEP, nullptr, pK);
    gemm_bf16x3<<<gg, 256, GEMM_SMEM>>>(pxh, pxl, pWth + 2 * WSTEP, pWtl + 2 * WSTEP, nullptr, pV);

    cudaMemsetAsync(pE, 0, N_BATCH * NHEADS * NHEADS * sizeof(float), 0);
    energy_kernel<<<dim3(N_BATCH, SEQ / ECHUNK), 256>>>();
    softmax_kernel<<<1, 64>>>();
    y_kernel<<<dim3(N_BATCH, SEQ / 16), 256>>>();

    gemm_bf16x3<<<gg, 256, GEMM_SMEM>>>(pYh, pYl, pWth + 3 * WSTEP, pWtl + 3 * WSTEP, bo, out);
}

// round 6
// speedup vs baseline: 3.3981x; 1.1584x over previous
#include <cuda_runtime.h>
#include <cuda_bf16.h>
#include <cuda_fp8.h>
#include <math.h>
#include <stdint.h>

#define N_BATCH 4
#define SEQ     4096
#define HID     1024
#define NHEADS  16
#define MROWS   (N_BATCH * SEQ)   // 16384

#define RSCALE 4096.0f
#define RISCALE (1.0f / 4096.0f)

// ---------------- scratch (device globals: no allocation allowed) ----------
__device__ __nv_bfloat16  g_xh  [MROWS * HID];     // x bf16 hi (row-major)
__device__ uint8_t        g_xh8 [MROWS * HID];     // x e4m3 hi
__device__ uint8_t        g_xl8 [MROWS * HID];     // x e4m3 lo*4096
__device__ __nv_bfloat16  g_xTh [MROWS * HID];     // x^T per batch [4][1024][4096] hi
__device__ __nv_bfloat16  g_xTl [MROWS * HID];     // x^T per batch lo
__device__ __nv_bfloat16  g_Gh  [N_BATCH * HID * HID];  // Gram hi
__device__ __nv_bfloat16  g_Gl  [N_BATCH * HID * HID];  // Gram lo
__device__ float          g_T   [N_BATCH * HID * HID];  // T = G @ Wk
__device__ float          g_V   [MROWS * HID];
__device__ __nv_bfloat16  g_Yh  [MROWS * HID];
__device__ uint8_t        g_Yh8 [MROWS * HID];
__device__ uint8_t        g_Yl8 [MROWS * HID];
__device__ __nv_bfloat16  g_Wkh [HID * HID];       // Wk^T bf16 hi [N,K]
__device__ __nv_bfloat16  g_Wkl [HID * HID];       // Wk^T bf16 lo
__device__ __nv_bfloat16  g_Wvh [HID * HID];       // Wv^T bf16 hi
__device__ uint8_t        g_Wv8h[HID * HID];
__device__ uint8_t        g_Wv8l[HID * HID];
__device__ __nv_bfloat16  g_Woh [HID * HID];       // Wo^T bf16 hi
__device__ uint8_t        g_Wo8h[HID * HID];
__device__ uint8_t        g_Wo8l[HID * HID];
__device__ float          g_E [N_BATCH * NHEADS * NHEADS];
__device__ float          g_A [N_BATCH * NHEADS * NHEADS];

// ======================= PTX helpers (baseline ISA) =========================
__device__ __forceinline__ uint32_t smem_u32(const void* p) {
    uint32_t a;
    asm("{ .reg .u64 t; cvta.to.shared.u64 t, %1; cvt.u32.u64 %0, t; }" : "=r"(a) : "l"(p));
    return a;
}
#define SWZ128(o) ((o) ^ (((o) >> 3) & 0x70))
#define SWZ64(o)  ((o) ^ (((o) >> 3) & 0x30))

__device__ __forceinline__ void cp_async16(uint32_t dst, const void* src) {
    asm volatile("cp.async.cg.shared.global [%0], [%1], 16;" :: "r"(dst), "l"(src));
}
#define CP_COMMIT() asm volatile("cp.async.commit_group;" ::: "memory")
#define CP_WAIT(n)  asm volatile("cp.async.wait_group %0;" :: "n"(n) : "memory")

__device__ __forceinline__ void ldsm_x4(uint32_t* r, uint32_t addr) {
    asm volatile("ldmatrix.sync.aligned.m8n8.x4.shared.b16 {%0,%1,%2,%3}, [%4];"
        : "=r"(r[0]), "=r"(r[1]), "=r"(r[2]), "=r"(r[3]) : "r"(addr));
}
__device__ __forceinline__ void mma_bf16(float* d, const uint32_t* a, const uint32_t* b) {
    asm volatile(
        "mma.sync.aligned.m16n8k16.row.col.f32.bf16.bf16.f32 "
        "{%0,%1,%2,%3}, {%4,%5,%6,%7}, {%8,%9}, {%0,%1,%2,%3};"
        : "+f"(d[0]), "+f"(d[1]), "+f"(d[2]), "+f"(d[3])
        : "r"(a[0]), "r"(a[1]), "r"(a[2]), "r"(a[3]), "r"(b[0]), "r"(b[1]));
}
__device__ __forceinline__ void mma_fp8(float* d, const uint32_t* a, const uint32_t* b) {
    asm volatile(
        "mma.sync.aligned.m16n8k32.row.col.f32.e4m3.e4m3.f32 "
        "{%0,%1,%2,%3}, {%4,%5,%6,%7}, {%8,%9}, {%0,%1,%2,%3};"
        : "+f"(d[0]), "+f"(d[1]), "+f"(d[2]), "+f"(d[3])
        : "r"(a[0]), "r"(a[1]), "r"(a[2]), "r"(a[3]), "r"(b[0]), "r"(b[1]));
}
__device__ __forceinline__ uint8_t f2e4m3(float v) {
    __nv_fp8_e4m3 t = __nv_fp8_e4m3(v);
    return *reinterpret_cast<uint8_t*>(&t);
}
__device__ __forceinline__ uint32_t pack2bf16(float a, float b) {
    __nv_bfloat162 t = __floats2bfloat162_rn(a, b);
    return *reinterpret_cast<uint32_t*>(&t);
}

// ======================= generic bf16x3 GEMM ================================
// C[M(128/CTA) x N(128/CTA)] = (Ah+Al)[M,K] @ (Bh+Bl)[N,K]^T  (3-term bf16)
// 3-stage cp.async ring; mode 0: write fp32 C; mode 1: write bf16 hi/lo pair
// (+ mirrored transposed block when symmetric && bx!=by).
#define STAGE3_BYTES 65536
#define GEMM3_SMEM   (3 * STAGE3_BYTES)

__global__ __launch_bounds__(256, 1)
void gemm3(const __nv_bfloat16* __restrict__ Ah_, const __nv_bfloat16* __restrict__ Al_,
           const __nv_bfloat16* __restrict__ Bh_, const __nv_bfloat16* __restrict__ Bl_,
           int lda, int ldb, int K,
           size_t sA, size_t sB, size_t sC,
           float* __restrict__ Cf_,
           __nv_bfloat16* __restrict__ Ch_, __nv_bfloat16* __restrict__ Cl_,
           int ldc, int mode, int symmetric)
{
    if (symmetric && (int)blockIdx.x < (int)blockIdx.y) return;
    extern __shared__ char smem[];
    const uint32_t sb = smem_u32(smem);
    const int tid  = threadIdx.x;
    const int wid  = tid >> 5, lane = tid & 31;
    const int wr   = wid >> 2, wc = wid & 3;
    const int z    = blockIdx.z;
    const int row0 = blockIdx.y * 128;   // output rows  (A rows)
    const int col0 = blockIdx.x * 128;   // output cols  (B rows)

    const __nv_bfloat16* base[4] = {
        Ah_ + (size_t)z * sA + (size_t)row0 * lda,
        Al_ + (size_t)z * sA + (size_t)row0 * lda,
        Bh_ + (size_t)z * sB + (size_t)col0 * ldb,
        Bl_ + (size_t)z * sB + (size_t)col0 * ldb };

    float acc[4][4][4];
#pragma unroll
    for (int mt = 0; mt < 4; mt++)
#pragma unroll
        for (int nt = 0; nt < 4; nt++)
#pragma unroll
            for (int e = 0; e < 4; e++) acc[mt][nt][e] = 0.0f;

    const int nst = K >> 6;

    auto issue = [&](int s) {
        const uint32_t st = sb + (s % 3) * STAGE3_BYTES;
        const int k0 = s * 64;
#pragma unroll
        for (int i = 0; i < 16; i++) {
            int c = tid + i * 256;
            int mat = c >> 10, j = c & 1023, row = j >> 3, q = j & 7;
            int ld = (mat < 2) ? lda : ldb;
            cp_async16(st + mat * 16384 + SWZ128((uint32_t)(row * 128 + q * 16)),
                       base[mat] + (size_t)row * ld + k0 + q * 8);
        }
        CP_COMMIT();
    };

    issue(0);
    issue(1);

    const int arow = wr * 64 + (lane & 15);
    const int brow = wc * 32 + (lane & 7) + ((lane >> 4) << 3);

    for (int s = 0; s < nst; s++) {
        if (s < nst - 1) CP_WAIT(1); else CP_WAIT(0);
        __syncthreads();
        if (s + 2 < nst) issue(s + 2);

        const uint32_t st = sb + (s % 3) * STAGE3_BYTES;
#pragma unroll
        for (int ks = 0; ks < 4; ks++) {
            uint32_t ah[4][4], al[4][4], bh[2][4], bl[2][4];
            const int abo = ks * 32 + (lane >> 4) * 16;
            const int bbo = ks * 32 + ((lane >> 3) & 1) * 16;
#pragma unroll
            for (int mt = 0; mt < 4; mt++) {
                uint32_t off = SWZ128((uint32_t)((arow + mt * 16) * 128 + abo));
                ldsm_x4(ah[mt], st + off);
                ldsm_x4(al[mt], st + 16384 + off);
            }
#pragma unroll
            for (int bt = 0; bt < 2; bt++) {
                uint32_t off = SWZ128((uint32_t)((brow + bt * 16) * 128 + bbo));
                ldsm_x4(bh[bt], st + 32768 + off);
                ldsm_x4(bl[bt], st + 49152 + off);
            }
#pragma unroll
            for (int mt = 0; mt < 4; mt++)
#pragma unroll
                for (int nt = 0; nt < 4; nt++) {
                    const uint32_t* bhp = &bh[nt >> 1][(nt & 1) * 2];
                    const uint32_t* blp = &bl[nt >> 1][(nt & 1) * 2];
                    mma_bf16(acc[mt][nt], ah[mt], bhp);
                    mma_bf16(acc[mt][nt], ah[mt], blp);
                    mma_bf16(acc[mt][nt], al[mt], bhp);
                }
        }
    }
    __syncthreads();

    // -------- epilogue via padded SMEM ---------------------------------
    float* Cs = reinterpret_cast<float*>(smem);   // [128][132]
    {
        const int r0 = wr * 64 + (lane >> 2);
        const int c0 = wc * 32 + (lane & 3) * 2;
#pragma unroll
        for (int mt = 0; mt < 4; mt++)
#pragma unroll
            for (int nt = 0; nt < 4; nt++) {
                int r = r0 + mt * 16, c = c0 + nt * 8;
                *reinterpret_cast<float2*>(&Cs[r * 132 + c]) =
                    make_float2(acc[mt][nt][0], acc[mt][nt][1]);
                *reinterpret_cast<float2*>(&Cs[(r + 8) * 132 + c]) =
                    make_float2(acc[mt][nt][2], acc[mt][nt][3]);
            }
    }
    __syncthreads();

    if (mode == 0) {
        float* C = Cf_ + (size_t)z * sC;
#pragma unroll
        for (int i = 0; i < 16; i++) {
            int idx = i * 256 + tid;
            int row = idx >> 5, q = idx & 31;
            float4 v = *reinterpret_cast<const float4*>(&Cs[row * 132 + q * 4]);
            *reinterpret_cast<float4*>(C + (size_t)(row0 + row) * ldc + col0 + q * 4) = v;
        }
    } else {
        __nv_bfloat16* Ch = Ch_ + (size_t)z * sC;
        __nv_bfloat16* Cl = Cl_ + (size_t)z * sC;
#pragma unroll
        for (int i = 0; i < 16; i++) {
            int idx = i * 256 + tid;
            int row = idx >> 5, q = idx & 31;
            float4 v = *reinterpret_cast<const float4*>(&Cs[row * 132 + q * 4]);
            float vv[4] = {v.x, v.y, v.z, v.w};
            uint32_t hp[2], lp[2];
            float h0 = __bfloat162float(__float2bfloat16_rn(vv[0]));
            float h1 = __bfloat162float(__float2bfloat16_rn(vv[1]));
            float h2 = __bfloat162float(__float2bfloat16_rn(vv[2]));
            float h3 = __bfloat162float(__float2bfloat16_rn(vv[3]));
            hp[0] = pack2bf16(vv[0], vv[1]); hp[1] = pack2bf16(vv[2], vv[3]);
            lp[0] = pack2bf16(vv[0] - h0, vv[1] - h1);
            lp[1] = pack2bf16(vv[2] - h2, vv[3] - h3);
            size_t o = (size_t)(row0 + row) * ldc + col0 + q * 4;
            *reinterpret_cast<uint2*>(Ch + o) = make_uint2(hp[0], hp[1]);
            *reinterpret_cast<uint2*>(Cl + o) = make_uint2(lp[0], lp[1]);
        }
        if (symmetric && blockIdx.x != blockIdx.y) {
            // mirrored transposed block at (col0, row0)
#pragma unroll
            for (int i = 0; i < 16; i++) {
                int idx = i * 256 + tid;
                int rp = idx >> 5, q = idx & 31;      // rp = original col
                float vv[4];
#pragma unroll
                for (int e = 0; e < 4; e++) vv[e] = Cs[(q * 4 + e) * 132 + rp];
                float h0 = __bfloat162float(__float2bfloat16_rn(vv[0]));
                float h1 = __bfloat162float(__float2bfloat16_rn(vv[1]));
                float h2 = __bfloat162float(__float2bfloat16_rn(vv[2]));
                float h3 = __bfloat162float(__float2bfloat16_rn(vv[3]));
                uint2 hp = make_uint2(pack2bf16(vv[0], vv[1]), pack2bf16(vv[2], vv[3]));
                uint2 lp = make_uint2(pack2bf16(vv[0] - h0, vv[1] - h1),
                                      pack2bf16(vv[2] - h2, vv[3] - h3));
                size_t o = (size_t)(col0 + rp) * ldc + row0 + q * 4;
                *reinterpret_cast<uint2*>(Ch + o) = hp;
                *reinterpret_cast<uint2*>(Cl + o) = lp;
            }
        }
    }
}

// ======================= mixed bf16 + fp8 GEMM (R5, proven) =================
#define STAGE_BYTES 65536
#define NSTAGE      3
#define GEMM_SMEM   (NSTAGE * STAGE_BYTES)
#define OFF_AH   0
#define OFF_BH   16384
#define OFF_A8H  32768
#define OFF_A8L  40960
#define OFF_B8H  49152
#define OFF_B8L  57344

__global__ __launch_bounds__(256, 1)
void gemm_mixed(const __nv_bfloat16* __restrict__ Agh,
                const uint8_t* __restrict__ Ag8h,
                const uint8_t* __restrict__ Ag8l,
                const __nv_bfloat16* __restrict__ Bgh,
                const uint8_t* __restrict__ Bg8h,
                const uint8_t* __restrict__ Bg8l,
                const float* __restrict__ bias,
                float* __restrict__ C)
{
    extern __shared__ char smem[];
    const uint32_t sb = smem_u32(smem);
    const int tid  = threadIdx.x;
    const int wid  = tid >> 5, lane = tid & 31;
    const int wr   = wid >> 2, wc = wid & 3;
    const int rowA0 = blockIdx.y * 128;
    const int rowB0 = blockIdx.x * 128;

    const __nv_bfloat16* pAh  = Agh  + (size_t)rowA0 * HID;
    const __nv_bfloat16* pBh  = Bgh  + (size_t)rowB0 * HID;
    const uint8_t*       pA8h = Ag8h + (size_t)rowA0 * HID;
    const uint8_t*       pA8l = Ag8l + (size_t)rowA0 * HID;
    const uint8_t*       pB8h = Bg8h + (size_t)rowB0 * HID;
    const uint8_t*       pB8l = Bg8l + (size_t)rowB0 * HID;

    float acc [4][4][4];
    float acc2[4][4][4];
#pragma unroll
    for (int mt = 0; mt < 4; mt++)
#pragma unroll
        for (int nt = 0; nt < 4; nt++)
#pragma unroll
            for (int e = 0; e < 4; e++) { acc[mt][nt][e] = 0.0f; acc2[mt][nt][e] = 0.0f; }

    auto issue = [&](int s) {
        const uint32_t st = sb + (s % NSTAGE) * STAGE_BYTES;
        const int k0 = s * 64;
#pragma unroll
        for (int i = 0; i < 16; i++) {
            int c = tid + i * 256;
            if (c < 2048) {
                int mat = c >> 10;
                int j = c & 1023, row = j >> 3, q = j & 7;
                const __nv_bfloat16* src = (mat ? pBh : pAh) + (size_t)row * HID + k0 + q * 8;
                cp_async16(st + mat * 16384 + SWZ128((uint32_t)(row * 128 + q * 16)), src);
            } else {
                int m2 = (c - 2048) >> 9;
                int j = c & 511, row = j >> 2, q = j & 3;
                const uint8_t* b8 = (m2 == 0) ? pA8h : (m2 == 1) ? pA8l
                                   : (m2 == 2) ? pB8h : pB8l;
                cp_async16(st + OFF_A8H + m2 * 8192 + SWZ64((uint32_t)(row * 64 + q * 16)),
                           b8 + (size_t)row * HID + k0 + q * 16);
            }
        }
        CP_COMMIT();
    };

    issue(0);
    issue(1);

    const int arow = wr * 64 + (lane & 15);
    const int brow = wc * 32 + (lane & 7) + ((lane >> 4) << 3);
    const int ar8  = wr * 64 + (lane & 7) + ((lane >> 3) & 1) * 8;
    const int akb  = ((lane >> 4) & 1) * 16;
    const int br8  = wc * 32 + (lane & 7) + ((lane >> 4) & 1) * 8;
    const int bkb  = ((lane >> 3) & 1) * 16;

    for (int s = 0; s < 16; s++) {
        if (s < 15) CP_WAIT(1); else CP_WAIT(0);
        __syncthreads();
        if (s + 2 < 16) issue(s + 2);

        const uint32_t st = sb + (s % NSTAGE) * STAGE_BYTES;
#pragma unroll
        for (int ks = 0; ks < 4; ks++) {
            uint32_t ah[4][4], bh[2][4];
            const int abo = ks * 32 + (lane >> 4) * 16;
            const int bbo = ks * 32 + ((lane >> 3) & 1) * 16;
#pragma unroll
            for (int mt = 0; mt < 4; mt++)
                ldsm_x4(ah[mt], st + OFF_AH + SWZ128((uint32_t)((arow + mt * 16) * 128 + abo)));
#pragma unroll
            for (int bt = 0; bt < 2; bt++)
                ldsm_x4(bh[bt], st + OFF_BH + SWZ128((uint32_t)((brow + bt * 16) * 128 + bbo)));
#pragma unroll
            for (int mt = 0; mt < 4; mt++)
#pragma unroll
                for (int nt = 0; nt < 4; nt++)
                    mma_bf16(acc[mt][nt], ah[mt], &bh[nt >> 1][(nt & 1) * 2]);
        }
#pragma unroll
        for (int kk = 0; kk < 2; kk++) {
            uint32_t a8h[4][4], a8l[4][4], b8h[2][4], b8l[2][4];
#pragma unroll
            for (int mt = 0; mt < 4; mt++) {
                uint32_t off = SWZ64((uint32_t)((ar8 + mt * 16) * 64 + kk * 32 + akb));
                ldsm_x4(a8h[mt], st + OFF_A8H + off);
                ldsm_x4(a8l[mt], st + OFF_A8L + off);
            }
#pragma unroll
            for (int bt = 0; bt < 2; bt++) {
                uint32_t off = SWZ64((uint32_t)((br8 + bt * 16) * 64 + kk * 32 + bkb));
                ldsm_x4(b8h[bt], st + OFF_B8H + off);
                ldsm_x4(b8l[bt], st + OFF_B8L + off);
            }
#pragma unroll
            for (int mt = 0; mt < 4; mt++)
#pragma unroll
                for (int nt = 0; nt < 4; nt++) {
                    mma_fp8(acc2[mt][nt], a8l[mt], &b8h[nt >> 1][(nt & 1) * 2]);
                    mma_fp8(acc2[mt][nt], a8h[mt], &b8l[nt >> 1][(nt & 1) * 2]);
                }
        }
    }
    __syncthreads();

    float* Cs = reinterpret_cast<float*>(smem);   // [128][132]
    {
        const int r0 = wr * 64 + (lane >> 2);
        const int c0 = wc * 32 + (lane & 3) * 2;
#pragma unroll
        for (int mt = 0; mt < 4; mt++)
#pragma unroll
            for (int nt = 0; nt < 4; nt++) {
                int r = r0 + mt * 16, c = c0 + nt * 8;
                float v0 = acc[mt][nt][0] + acc2[mt][nt][0] * RISCALE;
                float v1 = acc[mt][nt][1] + acc2[mt][nt][1] * RISCALE;
                float v2 = acc[mt][nt][2] + acc2[mt][nt][2] * RISCALE;
                float v3 = acc[mt][nt][3] + acc2[mt][nt][3] * RISCALE;
                *reinterpret_cast<float2*>(&Cs[r * 132 + c])       = make_float2(v0, v1);
                *reinterpret_cast<float2*>(&Cs[(r + 8) * 132 + c]) = make_float2(v2, v3);
            }
    }
    __syncthreads();

#pragma unroll
    for (int i = 0; i < 16; i++) {
        int idx = i * 256 + tid;
        int row = idx >> 5, q = idx & 31;
        float4 v = *reinterpret_cast<const float4*>(&Cs[row * 132 + q * 4]);
        int colg = rowB0 + q * 4;
        if (bias) {
            float4 b = *reinterpret_cast<const float4*>(bias + colg);
            v.x += b.x; v.y += b.y; v.z += b.z; v.w += b.w;
        }
        *reinterpret_cast<float4*>(C + (size_t)(rowA0 + row) * HID + colg) = v;
    }
}

// ============ x converts: straight bf16/fp8 + transposed bf16 hi/lo ========
__global__ __launch_bounds__(256)
void convert_x(const float* __restrict__ x)
{
    const int z = blockIdx.z;
    const int s0 = blockIdx.y * 32, c0 = blockIdx.x * 32;
    __shared__ float tile[32][33];
    const int tx = threadIdx.x & 31, ty = threadIdx.x >> 5;
    const float* xb = x + (size_t)z * SEQ * HID;

#pragma unroll
    for (int i = 0; i < 4; i++) {
        int r = ty * 4 + i;
        float v = xb[(size_t)(s0 + r) * HID + c0 + tx];
        tile[r][tx] = v;
        size_t o = ((size_t)z * SEQ + s0 + r) * HID + c0 + tx;
        __nv_bfloat16 h = __float2bfloat16_rn(v);
        g_xh [o] = h;
        g_xh8[o] = f2e4m3(v);
        g_xl8[o] = f2e4m3((v - __bfloat162float(h)) * RSCALE);
    }
    __syncthreads();
#pragma unroll
    for (int i = 0; i < 4; i++) {
        int cl = ty * 4 + i;
        float v = tile[tx][cl];
        __nv_bfloat16 h = __float2bfloat16_rn(v);
        size_t o = ((size_t)z * HID + c0 + cl) * SEQ + s0 + tx;
        g_xTh[o] = h;
        g_xTl[o] = __float2bfloat16_rn(v - __bfloat162float(h));
    }
}

// ===== W converts: z=0 Wk (bf16 hi/lo), z=1 Wv, z=2 Wo (bf16 hi + fp8) =====
__global__ __launch_bounds__(256)
void convert_w(const float* __restrict__ Wk, const float* __restrict__ Wv,
               const float* __restrict__ Wo)
{
    const int z = blockIdx.z;
    const float* W = (z == 0) ? Wk : (z == 1) ? Wv : Wo;
    __shared__ float tile[32][33];
    const int tx = threadIdx.x & 31, ty = threadIdx.x >> 5;
    const int bx = blockIdx.x, by = blockIdx.y;
#pragma unroll
    for (int i = 0; i < 4; i++) {
        int kl = ty * 4 + i;
        tile[kl][tx] = W[(size_t)(by * 32 + kl) * HID + bx * 32 + tx];
    }
    __syncthreads();
#pragma unroll
    for (int i = 0; i < 4; i++) {
        int nl = ty * 4 + i;
        float v = tile[tx][nl];
        __nv_bfloat16 h = __float2bfloat16_rn(v);
        float lo = v - __bfloat162float(h);
        size_t o = (size_t)(bx * 32 + nl) * HID + by * 32 + tx;
        if (z == 0) {
            g_Wkh[o] = h;
            g_Wkl[o] = __float2bfloat16_rn(lo);
        } else if (z == 1) {
            g_Wvh[o] = h;
            g_Wv8h[o] = f2e4m3(v);
            g_Wv8l[o] = f2e4m3(lo * RSCALE);
        } else {
            g_Woh[o] = h;
            g_Wo8h[o] = f2e4m3(v);
            g_Wo8l[o] = f2e4m3(lo * RSCALE);
        }
    }
}

// -------- E[n,a,b] = sum_{i,d} Wq[i, a*64+d] * T[n][i, b*64+d] --------------
__global__ __launch_bounds__(256)
void ereduce(const float* __restrict__ Wq)
{
    const int n  = blockIdx.x;
    const int i0 = blockIdx.y * 16;
    const int tid = threadIdx.x;
    const int a = tid & 15, b = tid >> 4;

    __shared__ float qs[4][1088];
    __shared__ float ks[4][1088];

    const float* Tb = g_T + (size_t)n * HID * HID;

    float acc = 0.0f;
    for (int batch = 0; batch < 4; batch++) {
        const int irow = i0 + batch * 4;
#pragma unroll
        for (int t = 0; t < 8; t++) {
            int f  = tid + t * 256;
            int ff = f & 1023;
            int rl = ff >> 8;
            int ch = ff & 255;
            const float* src = ((f < 1024) ? Wq : Tb) + (size_t)(irow + rl) * HID + ch * 4;
            float4 v = *reinterpret_cast<const float4*>(src);
            float* dst = (f < 1024) ? qs[rl] : ks[rl];
            int c = ch * 4, d0 = c & 63, h = c >> 6;
            dst[(d0 + 0) * 17 + h] = v.x;
            dst[(d0 + 1) * 17 + h] = v.y;
            dst[(d0 + 2) * 17 + h] = v.z;
            dst[(d0 + 3) * 17 + h] = v.w;
        }
        __syncthreads();
#pragma unroll
        for (int rl = 0; rl < 4; rl++)
#pragma unroll
            for (int d = 0; d < 64; d++)
                acc = fmaf(qs[rl][d * 17 + a], ks[rl][d * 17 + b], acc);
        __syncthreads();
    }
    atomicAdd(&g_E[n * 256 + a * 16 + b], acc);
}

// ---------------- softmax over b ------------------------------------------
__global__ void softmax_kernel()
{
    int t = threadIdx.x;
    if (t >= N_BATCH * NHEADS) return;
    int n = t >> 4, a = t & 15;
    const float* e = g_E + n * 256 + a * 16;
    float v[16], m = -1e30f;
#pragma unroll
    for (int b = 0; b < 16; b++) { v[b] = e[b] * 0.125f; m = fmaxf(m, v[b]); }
    float s = 0.0f;
#pragma unroll
    for (int b = 0; b < 16; b++) { v[b] = expf(v[b] - m); s += v[b]; }
    float inv = 1.0f / s;
    float* o = g_A + n * 256 + a * 16;
#pragma unroll
    for (int b = 0; b < 16; b++) o[b] = v[b] * inv;
}

// ------ Y[n, a*256+u, r*64+d] = sum_b attn[n,a,b] V[n,16u+r,b*64+d] --------
__global__ __launch_bounds__(256)
void y_kernel()
{
    const int n = blockIdx.x, u = blockIdx.y;
    __shared__ float at[256];
    at[threadIdx.x] = g_A[n * 256 + threadIdx.x];
    __syncthreads();

    const float* Vb = g_V + ((size_t)n * SEQ + (size_t)u * 16) * HID;
    size_t ybase = (size_t)n * SEQ * HID + (size_t)u * HID;

    for (int j = threadIdx.x; j < HID; j += 256) {
        int r = j >> 6, d = j & 63;
        float v[16];
#pragma unroll
        for (int b = 0; b < 16; b++)
            v[b] = Vb[(size_t)r * HID + b * 64 + d];
#pragma unroll
        for (int a = 0; a < 16; a++) {
            float acc = 0.0f;
#pragma unroll
            for (int b = 0; b < 16; b++)
                acc = fmaf(at[a * 16 + b], v[b], acc);
            size_t o = ybase + (size_t)a * 256 * HID + j;
            __nv_bfloat16 h = __float2bfloat16_rn(acc);
            g_Yh [o] = h;
            g_Yh8[o] = f2e4m3(acc);
            g_Yl8[o] = f2e4m3((acc - __bfloat162float(h)) * RSCALE);
        }
    }
}

// ---------------- launch ----------------------------------------------------
extern "C" void kernel_launch(void* const* d_in, const int* in_sizes, int n_in,
                              void* d_out, int out_size)
{
    const float* x  = (const float*)d_in[0];
    const float* Wq = (const float*)d_in[1];
    const float* Wk = (const float*)d_in[2];
    const float* Wv = (const float*)d_in[3];
    const float* Wo = (const float*)d_in[4];
    const float* bo = (const float*)d_in[5];
    float* out = (float*)d_out;

    float *pT, *pV, *pE;
    __nv_bfloat16 *pxh, *pxTh, *pxTl, *pGh, *pGl, *pYh;
    __nv_bfloat16 *pWkh, *pWkl, *pWvh, *pWoh;
    uint8_t *pxh8, *pxl8, *pYh8, *pYl8, *pWv8h, *pWv8l, *pWo8h, *pWo8l;
    cudaGetSymbolAddress((void**)&pT,  g_T);
    cudaGetSymbolAddress((void**)&pV,  g_V);
    cudaGetSymbolAddress((void**)&pE,  g_E);
    cudaGetSymbolAddress((void**)&pxh, g_xh);
    cudaGetSymbolAddress((void**)&pxh8, g_xh8);
    cudaGetSymbolAddress((void**)&pxl8, g_xl8);
    cudaGetSymbolAddress((void**)&pxTh, g_xTh);
    cudaGetSymbolAddress((void**)&pxTl, g_xTl);
    cudaGetSymbolAddress((void**)&pGh, g_Gh);
    cudaGetSymbolAddress((void**)&pGl, g_Gl);
    cudaGetSymbolAddress((void**)&pYh, g_Yh);
    cudaGetSymbolAddress((void**)&pYh8, g_Yh8);
    cudaGetSymbolAddress((void**)&pYl8, g_Yl8);
    cudaGetSymbolAddress((void**)&pWkh, g_Wkh);
    cudaGetSymbolAddress((void**)&pWkl, g_Wkl);
    cudaGetSymbolAddress((void**)&pWvh, g_Wvh);
    cudaGetSymbolAddress((void**)&pWoh, g_Woh);
    cudaGetSymbolAddress((void**)&pWv8h, g_Wv8h);
    cudaGetSymbolAddress((void**)&pWv8l, g_Wv8l);
    cudaGetSymbolAddress((void**)&pWo8h, g_Wo8h);
    cudaGetSymbolAddress((void**)&pWo8l, g_Wo8l);

    cudaFuncSetAttribute(gemm3, cudaFuncAttributeMaxDynamicSharedMemorySize, GEMM3_SMEM);
    cudaFuncSetAttribute(gemm_mixed, cudaFuncAttributeMaxDynamicSharedMemorySize, GEMM_SMEM);

    // converts
    convert_x<<<dim3(HID / 32, SEQ / 32, N_BATCH), 256>>>(x);
    convert_w<<<dim3(HID / 32, HID / 32, 3), 256>>>(Wk, Wv, Wo);

    // Gram: G[n] = x[n]^T x[n]   (symmetric, bf16x3, output bf16 hi/lo)
    gemm3<<<dim3(8, 8, N_BATCH), 256, GEMM3_SMEM>>>(
        pxTh, pxTl, pxTh, pxTl, SEQ, SEQ, SEQ,
        (size_t)HID * SEQ, (size_t)HID * SEQ, (size_t)HID * HID,
        nullptr, pGh, pGl, HID, 1, 1);

    // T[n] = G[n] @ Wk   (bf16x3, fp32 out)
    gemm3<<<dim3(8, 8, N_BATCH), 256, GEMM3_SMEM>>>(
        pGh, pGl, pWkh, pWkl, HID, HID, HID,
        (size_t)HID * HID, 0, (size_t)HID * HID,
        pT, nullptr, nullptr, HID, 0, 0);

    // E, softmax
    cudaMemsetAsync(pE, 0, N_BATCH * NHEADS * NHEADS * sizeof(float), 0);
    ereduce<<<dim3(N_BATCH, HID / 16), 256>>>(Wq);
    softmax_kernel<<<1, 64>>>();

    // V = x @ Wv  (mixed bf16+fp8)
    gemm_mixed<<<dim3(HID / 128, MROWS / 128), 256, GEMM_SMEM>>>(
        pxh, pxh8, pxl8, pWvh, pWv8h, pWv8l, nullptr, pV);

    y_kernel<<<dim3(N_BATCH, SEQ / 16), 256>>>();

    // out = Y @ Wo + bo  (mixed bf16+fp8)
    gemm_mixed<<<dim3(HID / 128, MROWS / 128), 256, GEMM_SMEM>>>(
        pYh, pYh8, pYl8, pWoh, pWo8h, pWo8l, bo, out);
}